// round 2
// baseline (speedup 1.0000x reference)
#include <cuda_runtime.h>
#include <cuda_bf16.h>

// Problem constants (fixed by setup_inputs)
#define Hh 64
#define Ww 64
#define Cc 128
#define Dd 256
#define R1 8
#define R2 4
#define CK 8          // channel chunk
#define TH 8          // pixel tile height
#define TW 32         // pixel tile width
#define XCOLS 34      // TW + 2 halo
#define XROWS 10      // TH + 2 halo
#define XSTRIDE 35    // odd stride -> conflict-free LDS pattern

// Reconstructed conv weights in [C][D][9] layout (contiguous per (c, dblk) chunk)
__device__ float g_W[Cc * Dd * 9];

// ---------------------------------------------------------------------------
// Kernel 1: build W[c][d][9] = sum_r core0[d,c,r] * (sum_s core1[d,r,kh,s]*core2[d,s,kw])
// One block per d (256 blocks), 128 threads (one per c).
// ---------------------------------------------------------------------------
__global__ void build_w_kernel(const float* __restrict__ core0,
                               const float* __restrict__ core1,
                               const float* __restrict__ core2) {
    int d = blockIdx.x;
    int tid = threadIdx.x;
    __shared__ float sA[R1 * 9];

    if (tid < R1 * 9) {
        int r = tid / 9;
        int k = tid % 9;
        int kh = k / 3, kw = k % 3;
        float a = 0.f;
        #pragma unroll
        for (int s = 0; s < R2; s++)
            a += core1[d * (R1 * 3 * R2) + r * (3 * R2) + kh * R2 + s] *
                 core2[d * (R2 * 3) + s * 3 + kw];
        sA[tid] = a;
    }
    __syncthreads();

    int c = tid;  // 0..127
    float cr[R1];
    #pragma unroll
    for (int r = 0; r < R1; r++)
        cr[r] = core0[d * (Cc * R1) + c * R1 + r];

    #pragma unroll
    for (int k = 0; k < 9; k++) {
        float w = 0.f;
        #pragma unroll
        for (int r = 0; r < R1; r++)
            w += cr[r] * sA[r * 9 + k];
        g_W[(size_t)c * (Dd * 9) + d * 9 + k] = w;
    }
}

// ---------------------------------------------------------------------------
// Kernel 2: tiled implicit-GEMM conv.
// Grid: (16 tiles [2 wide x 8 tall], 4 d-blocks, 32 images). Block: 256 threads.
// Thread (tc = tid>>5, tp = tid&31): 8 channels (tc*8..+7) x 8 pixels
// (row py0 = tp>>2, cols px0 = (tp&3)*8 .. +7).
// ---------------------------------------------------------------------------
__global__ void __launch_bounds__(256, 2)
ttconv_kernel(const float* __restrict__ x,
              const float* __restrict__ bias,
              float* __restrict__ out) {
    __shared__ float sX[CK][XROWS][XSTRIDE];
    __shared__ float sW[CK][64][9];

    const int tid  = threadIdx.x;
    const int tc   = tid >> 5;
    const int tp   = tid & 31;
    const int px0  = (tp & 3) * 8;
    const int py0  = tp >> 2;

    const int tileX = (blockIdx.x & 1) * TW;
    const int tileY = (blockIdx.x >> 1) * TH;
    const int dblk  = blockIdx.y;
    const int n     = blockIdx.z;

    const float* xn = x + (size_t)n * Cc * Hh * Ww;

    float acc[8][8];
    #pragma unroll
    for (int i = 0; i < 8; i++)
        #pragma unroll
        for (int j = 0; j < 8; j++)
            acc[i][j] = 0.f;

    for (int c0 = 0; c0 < Cc; c0 += CK) {
        __syncthreads();  // previous chunk's reads done before overwrite

        // ---- load x chunk (with halo, zero-padded at borders) ----
        for (int idx = tid; idx < CK * XROWS * XCOLS; idx += 256) {
            int cc  = idx / (XROWS * XCOLS);
            int rem = idx % (XROWS * XCOLS);
            int row = rem / XCOLS;
            int col = rem % XCOLS;
            int gy = tileY - 1 + row;
            int gx = tileX - 1 + col;
            float v = 0.f;
            if ((unsigned)gy < Hh && (unsigned)gx < Ww)
                v = xn[(size_t)(c0 + cc) * (Hh * Ww) + gy * Ww + gx];
            sX[cc][row][col] = v;
        }

        // ---- load W chunk: fully coalesced thanks to [C][D][9] layout ----
        {
            const float* wg = g_W + (size_t)c0 * (Dd * 9) + dblk * 576;
            float* sWf = &sW[0][0][0];
            for (int idx = tid; idx < CK * 576; idx += 256) {
                int cc  = idx / 576;
                int rem = idx % 576;
                sWf[idx] = wg[(size_t)cc * (Dd * 9) + rem];
            }
        }

        __syncthreads();

        // ---- compute ----
        for (int cc = 0; cc < CK; cc++) {
            #pragma unroll
            for (int kh = 0; kh < 3; kh++) {
                float xrow[10];
                #pragma unroll
                for (int j = 0; j < 10; j++)
                    xrow[j] = sX[cc][py0 + kh][px0 + j];
                #pragma unroll
                for (int kw = 0; kw < 3; kw++) {
                    float wv[8];
                    #pragma unroll
                    for (int dd = 0; dd < 8; dd++)
                        wv[dd] = sW[cc][tc * 8 + dd][kh * 3 + kw];
                    #pragma unroll
                    for (int dd = 0; dd < 8; dd++)
                        #pragma unroll
                        for (int pp = 0; pp < 8; pp++)
                            acc[dd][pp] += wv[dd] * xrow[pp + kw];
                }
            }
        }
    }

    // ---- epilogue: add bias, write out (float4 stores, 16B aligned) ----
    const float b = __ldg(bias);
    const int ybase = tileY + py0;
    const int xbase = tileX + px0;
    #pragma unroll
    for (int dd = 0; dd < 8; dd++) {
        int d = dblk * 64 + tc * 8 + dd;
        float* op = out + ((size_t)n * Dd + d) * (Hh * Ww) + ybase * Ww + xbase;
        float4 v0 = make_float4(acc[dd][0] + b, acc[dd][1] + b,
                                acc[dd][2] + b, acc[dd][3] + b);
        float4 v1 = make_float4(acc[dd][4] + b, acc[dd][5] + b,
                                acc[dd][6] + b, acc[dd][7] + b);
        *reinterpret_cast<float4*>(op)     = v0;
        *reinterpret_cast<float4*>(op + 4) = v1;
    }
}

// ---------------------------------------------------------------------------
// Launch: inputs in metadata order: x, core0, core1, core2, bias, stride, pad.
// stride=1, pad=1 are fixed by the problem; hardcoded.
// ---------------------------------------------------------------------------
extern "C" void kernel_launch(void* const* d_in, const int* in_sizes, int n_in,
                              void* d_out, int out_size) {
    const float* x     = (const float*)d_in[0];
    const float* core0 = (const float*)d_in[1];
    const float* core1 = (const float*)d_in[2];
    const float* core2 = (const float*)d_in[3];
    const float* bias  = (const float*)d_in[4];
    float* out = (float*)d_out;

    build_w_kernel<<<Dd, Cc>>>(core0, core1, core2);

    dim3 grid(16, 4, 32);  // 16 spatial tiles (2x8), 4 d-blocks, 32 images
    ttconv_kernel<<<grid, 256>>>(x, bias, out);
}

// round 5
// speedup vs baseline: 2.5030x; 2.5030x over previous
#include <cuda_runtime.h>
#include <cstdint>

#define Hh 64
#define Ww 64
#define Cc 128
#define Dd 256
#define NIMG 32
#define KTOT 1152
#define NCH 72              // K chunks of 16

// Reconstructed tf32 weights, chunked: [chunk][kk=16][d=256]
__device__ float g_A[NCH * 4096];

static __device__ __forceinline__ float rntf32(float a) {
    float r; asm("cvt.rna.tf32.f32 %0, %1;" : "=f"(r) : "f"(a)); return r;
}

// ---------------------------------------------------------------------------
// Build A: W[d][k] = sum_r core0[d,c,r] * (sum_s core1[d,r,kh,s]*core2[d,s,kw]),
// k = c*9 + (kh*3+kw). One block per d, thread = c.
// ---------------------------------------------------------------------------
__global__ void build_A_kernel(const float* __restrict__ c0,
                               const float* __restrict__ c1,
                               const float* __restrict__ c2) {
    int d = blockIdx.x, t = threadIdx.x;
    __shared__ float sA[72];
    if (t < 72) {
        int r = t / 9, k = t % 9, kh = k / 3, kw = k % 3;
        float a = 0.f;
        #pragma unroll
        for (int s = 0; s < 4; s++)
            a += c1[d * 96 + r * 12 + kh * 4 + s] * c2[d * 12 + s * 3 + kw];
        sA[t] = a;
    }
    __syncthreads();
    int c = t;
    float cr[8];
    #pragma unroll
    for (int r = 0; r < 8; r++) cr[r] = c0[d * 1024 + c * 8 + r];
    #pragma unroll
    for (int tap = 0; tap < 9; tap++) {
        float w = 0.f;
        #pragma unroll
        for (int r = 0; r < 8; r++) w += cr[r] * sA[r * 9 + tap];
        int k = c * 9 + tap;
        g_A[(k >> 4) * 4096 + (k & 15) * 256 + d] = rntf32(w);
    }
}

// ---------------------------------------------------------------------------
// Main: im2col GEMM-conv with mma.sync m16n8k8 tf32.
// Grid (2 dblk, 32 row-pairs, 32 imgs). 256 threads = 8 warps (2 M x 4 N).
// CTA tile: 128 d x 128 px (2 y-rows x 64 x). Warp tile 64x32. K chunk 16.
// ---------------------------------------------------------------------------
__global__ void __launch_bounds__(256, 2)
conv_main(const float* __restrict__ x, const float* __restrict__ bias,
          float* __restrict__ out) {
    __shared__ float sA[2][16 * 136];   // [k][m], row stride 136 (conflict-free)
    __shared__ float sB[2][16 * 136];   // [k][n]

    const int tid = threadIdx.x;
    const int wid = tid >> 5, lid = tid & 31;
    const int g = lid >> 2, tig = lid & 3;
    const int warp_m = wid & 1, warp_n = wid >> 1;
    const int dblk = blockIdx.x;
    const int y0 = blockIdx.y * 2;
    const int img = blockIdx.z;

    // gather mapping: thread -> (kk row of B, 8-px segment)
    const int kk = tid >> 4;
    const int seg = tid & 15;
    const int n0 = seg * 8;
    const int yy = y0 + (n0 >> 6);      // output y for this thread's segment
    const int xb0 = n0 & 63;
    const float* xim = x + (size_t)img * Cc * Hh * Ww;

    float acc[4][4][4];
    #pragma unroll
    for (int mt = 0; mt < 4; mt++)
        #pragma unroll
        for (int nt = 0; nt < 4; nt++)
            #pragma unroll
            for (int i = 0; i < 4; i++) acc[mt][nt][i] = 0.f;

    float4 rA0, rA1;
    float rB[8];

    // A-store mapping (chunk is [16 kk][256 d]; this CTA takes d-half dblk)
    const int ka = tid >> 5;            // kk row 0..7 (rA0), +8 (rA1)
    const int ma = (tid * 4) & 127;     // d_local 0..124

    // -------- gather chunk into regs --------
    auto gather = [&](int chunk) {
        const float4* Ag = (const float4*)(g_A + chunk * 4096 + dblk * 128);
        rA0 = Ag[ka * 64 + (ma >> 2)];
        rA1 = Ag[(ka + 8) * 64 + (ma >> 2)];
        int k = chunk * 16 + kk;
        int c = k / 9, tap = k - c * 9;
        int kh = tap / 3, kw = tap - kh * 3;
        int gy = yy + kh - 1;
        const float* xrow = xim + (size_t)c * 4096 + gy * 64;
        int gxb = xb0 + kw - 1;
        bool rowok = (unsigned)gy < Hh;
        #pragma unroll
        for (int j = 0; j < 8; j++) {
            int gx = gxb + j;
            float v = (rowok && (unsigned)gx < Ww) ? xrow[gx] : 0.f;
            rB[j] = rntf32(v);
        }
    };
    // -------- regs -> smem --------
    auto store = [&](int buf) {
        *(float4*)&sA[buf][ka * 136 + ma]       = rA0;
        *(float4*)&sA[buf][(ka + 8) * 136 + ma] = rA1;
        *(float4*)&sB[buf][kk * 136 + n0]     = make_float4(rB[0], rB[1], rB[2], rB[3]);
        *(float4*)&sB[buf][kk * 136 + n0 + 4] = make_float4(rB[4], rB[5], rB[6], rB[7]);
    };
    // -------- 32 mma on a smem buffer --------
    auto domma = [&](int buf) {
        const float* As = sA[buf];
        const float* Bs = sB[buf];
        #pragma unroll
        for (int ks = 0; ks < 2; ks++) {
            const int r0 = (ks * 8 + tig) * 136;
            const int r4 = r0 + 4 * 136;
            uint32_t af[4][4], bf[4][2];
            #pragma unroll
            for (int mt = 0; mt < 4; mt++) {
                int m = warp_m * 64 + mt * 16 + g;
                af[mt][0] = __float_as_uint(As[r0 + m]);
                af[mt][1] = __float_as_uint(As[r0 + m + 8]);
                af[mt][2] = __float_as_uint(As[r4 + m]);
                af[mt][3] = __float_as_uint(As[r4 + m + 8]);
            }
            #pragma unroll
            for (int nt = 0; nt < 4; nt++) {
                int n = warp_n * 32 + nt * 8 + g;
                bf[nt][0] = __float_as_uint(Bs[r0 + n]);
                bf[nt][1] = __float_as_uint(Bs[r4 + n]);
            }
            #pragma unroll
            for (int mt = 0; mt < 4; mt++)
                #pragma unroll
                for (int nt = 0; nt < 4; nt++)
                    asm volatile(
                        "mma.sync.aligned.m16n8k8.row.col.f32.tf32.tf32.f32 "
                        "{%0,%1,%2,%3}, {%4,%5,%6,%7}, {%8,%9}, {%0,%1,%2,%3};"
                        : "+f"(acc[mt][nt][0]), "+f"(acc[mt][nt][1]),
                          "+f"(acc[mt][nt][2]), "+f"(acc[mt][nt][3])
                        : "r"(af[mt][0]), "r"(af[mt][1]), "r"(af[mt][2]), "r"(af[mt][3]),
                          "r"(bf[nt][0]), "r"(bf[nt][1]));
        }
    };

    // -------- pipelined main loop --------
    gather(0);
    store(0);
    __syncthreads();
    for (int chunk = 0; chunk < NCH; ++chunk) {
        const int buf = chunk & 1;
        if (chunk + 1 < NCH) gather(chunk + 1);   // LDG latency hides under mma
        domma(buf);
        if (chunk + 1 < NCH) store(buf ^ 1);
        __syncthreads();
    }

    // -------- epilogue --------
    const float b = __ldg(bias);
    #pragma unroll
    for (int mt = 0; mt < 4; mt++) {
        int d = dblk * 128 + warp_m * 64 + mt * 16 + g;
        #pragma unroll
        for (int nt = 0; nt < 4; nt++) {
            int px = warp_n * 32 + nt * 8 + tig * 2;
            int oy = y0 + (px >> 6);
            int ox = px & 63;
            float* o0 = out + (((size_t)img * Dd + d) * Hh + oy) * Ww + ox;
            float* o1 = out + (((size_t)img * Dd + d + 8) * Hh + oy) * Ww + ox;
            *(float2*)o0 = make_float2(acc[mt][nt][0] + b, acc[mt][nt][1] + b);
            *(float2*)o1 = make_float2(acc[mt][nt][2] + b, acc[mt][nt][3] + b);
        }
    }
}

// ---------------------------------------------------------------------------
extern "C" void kernel_launch(void* const* d_in, const int* in_sizes, int n_in,
                              void* d_out, int out_size) {
    const float* x     = (const float*)d_in[0];
    const float* core0 = (const float*)d_in[1];
    const float* core1 = (const float*)d_in[2];
    const float* core2 = (const float*)d_in[3];
    const float* bias  = (const float*)d_in[4];
    float* out = (float*)d_out;

    build_A_kernel<<<Dd, Cc>>>(core0, core1, core2);

    dim3 grid(2, 32, 32);   // dblk, row-pairs, imgs
    conv_main<<<grid, 256>>>(x, bias, out);
}